// round 11
// baseline (speedup 1.0000x reference)
#include <cuda_runtime.h>
#include <cuda_bf16.h>
#include <math.h>
#include <stdint.h>

#define D_MODEL 1024
#define NHEADS  16
#define DK      64
#define SEQ     2048
#define BATCH   2
#define NTOK    (BATCH*SEQ)   // 4096
#define DFF     4096

// ---------------- scratch (no allocations allowed) ----------------
__device__ float g_ctx[NTOK*D_MODEL];
__device__ float g_s1 [NTOK*D_MODEL];
__device__ float g_x1 [NTOK*D_MODEL];
__device__ float g_ff [NTOK*DFF];
__device__ float g_s2 [NTOK*D_MODEL];

// attention operands (bf16 hi/lo, q pre-scaled by 1/8)
__device__ __nv_bfloat16 g_qkvh[3*NTOK*D_MODEL];
__device__ __nv_bfloat16 g_qkvl[3*NTOK*D_MODEL];

// int8 quantized activations (hi/lo split) + per-row scales
__device__ int8_t g_xq1 [NTOK*D_MODEL];  __device__ int8_t g_xq0 [NTOK*D_MODEL];
__device__ int8_t g_cq1 [NTOK*D_MODEL];  __device__ int8_t g_cq0 [NTOK*D_MODEL];
__device__ int8_t g_x1q1[NTOK*D_MODEL];  __device__ int8_t g_x1q0[NTOK*D_MODEL];
__device__ int8_t g_ffq1[NTOK*DFF];      __device__ int8_t g_ffq0[NTOK*DFF];
__device__ float  g_sx[NTOK], g_sctx[NTOK], g_sx1[NTOK], g_sff[NTOK];

// int8 quantized transposed weights [N][K] + per-N scales
__device__ int8_t g_wqkv1[3*D_MODEL*D_MODEL]; __device__ int8_t g_wqkv0[3*D_MODEL*D_MODEL];
__device__ int8_t g_wo1 [D_MODEL*D_MODEL];    __device__ int8_t g_wo0 [D_MODEL*D_MODEL];
__device__ int8_t g_w11 [DFF*D_MODEL];        __device__ int8_t g_w10 [DFF*D_MODEL];
__device__ int8_t g_w21 [D_MODEL*DFF];        __device__ int8_t g_w20 [D_MODEL*DFF];
__device__ float  g_swqkv[3*D_MODEL], g_swo[D_MODEL], g_sw1[DFF], g_sw2[D_MODEL];

// ---------------- helpers ----------------
__device__ __forceinline__ uint32_t smem_u32(const void* p) {
    uint32_t a;
    asm("{ .reg .u64 t; cvta.to.shared.u64 t, %1; cvt.u32.u64 %0, t; }" : "=r"(a) : "l"(p));
    return a;
}
__device__ __forceinline__ void ldsm4(uint32_t* r, uint32_t addr) {
    asm volatile("ldmatrix.sync.aligned.m8n8.x4.shared.b16 {%0,%1,%2,%3}, [%4];"
        : "=r"(r[0]), "=r"(r[1]), "=r"(r[2]), "=r"(r[3]) : "r"(addr));
}
__device__ __forceinline__ void ldsm4t(uint32_t* r, uint32_t addr) {
    asm volatile("ldmatrix.sync.aligned.m8n8.x4.trans.shared.b16 {%0,%1,%2,%3}, [%4];"
        : "=r"(r[0]), "=r"(r[1]), "=r"(r[2]), "=r"(r[3]) : "r"(addr));
}
__device__ __forceinline__ void mma_bf16(float* d, const uint32_t* a, const uint32_t* b) {
    asm volatile(
        "mma.sync.aligned.m16n8k16.row.col.f32.bf16.bf16.f32 "
        "{%0,%1,%2,%3}, {%4,%5,%6,%7}, {%8,%9}, {%0,%1,%2,%3};"
        : "+f"(d[0]), "+f"(d[1]), "+f"(d[2]), "+f"(d[3])
        : "r"(a[0]), "r"(a[1]), "r"(a[2]), "r"(a[3]), "r"(b[0]), "r"(b[1]));
}
__device__ __forceinline__ void mma_s8(int* d, const uint32_t* a, const uint32_t* b) {
    asm volatile(
        "mma.sync.aligned.m16n8k32.row.col.s32.s8.s8.s32 "
        "{%0,%1,%2,%3}, {%4,%5,%6,%7}, {%8,%9}, {%0,%1,%2,%3};"
        : "+r"(d[0]), "+r"(d[1]), "+r"(d[2]), "+r"(d[3])
        : "r"(a[0]), "r"(a[1]), "r"(a[2]), "r"(a[3]), "r"(b[0]), "r"(b[1]));
}
__device__ __forceinline__ uint32_t packbf2(float x, float y) {
    __nv_bfloat162 h = __floats2bfloat162_rn(x, y);
    return *(uint32_t*)&h;
}
__device__ __forceinline__ uint32_t packbf16pair(__nv_bfloat16 a, __nv_bfloat16 b) {
    return (uint32_t)__bfloat16_as_ushort(a) | ((uint32_t)__bfloat16_as_ushort(b) << 16);
}
__device__ __forceinline__ float fexp(float x) {
    float y = x * 1.4426950408889634f;
    y = fmaxf(y, -126.0f);
    float t = y + 12582912.0f;
    int   n = __float_as_int(t) - 0x4B400000;
    float f = y - (t - 12582912.0f);
    float p = 1.3333558146428443e-3f;
    p = fmaf(p, f, 9.6181291076284772e-3f);
    p = fmaf(p, f, 5.5504108664821580e-2f);
    p = fmaf(p, f, 2.4022650695910072e-1f);
    p = fmaf(p, f, 6.9314718055994531e-1f);
    p = fmaf(p, f, 1.0f);
    return __int_as_float(__float_as_int(p) + (n << 23));
}
// split f (already scaled by 1/s) into hi/lo int8 pair: f ~= 128*h + l
__device__ __forceinline__ void split_i8(float f, int8_t& h8, int8_t& l8) {
    float h = rintf(f * 0.0078125f);            // f/128, |h| <= 127
    float l = rintf(fmaf(-128.f, h, f));        // |l| <= 64
    h8 = (int8_t)(int)h;
    l8 = (int8_t)(int)l;
}

// ---------------- weight prep ----------------
// per-output-column max of W[K][N] -> scale s[n] = max/16256
__global__ __launch_bounds__(256) void wcolmax(const float* __restrict__ W,
                                               float* __restrict__ s, int K, int N)
{
    const int n = blockIdx.x * 256 + threadIdx.x;
    float m = 1e-20f;
    for (int k = 0; k < K; k++) m = fmaxf(m, fabsf(W[(size_t)k * N + n]));
    s[n] = m * (1.0f / 16256.0f);
}
// W[K][N] fp32 -> transposed int8 hi/lo [N][K]
__global__ __launch_bounds__(256) void wquant(const float* __restrict__ W,
                                              const float* __restrict__ s,
                                              int8_t* __restrict__ T1, int8_t* __restrict__ T0,
                                              int K, int N)
{
    __shared__ float t[32][33];
    const int k0 = blockIdx.y * 32, n0 = blockIdx.x * 32;
    const int tx = threadIdx.x, ty = threadIdx.y;
#pragma unroll
    for (int r = 0; r < 4; r++)
        t[ty + 8*r][tx] = W[(size_t)(k0 + ty + 8*r) * N + n0 + tx];
    __syncthreads();
#pragma unroll
    for (int r = 0; r < 4; r++) {
        const int n = n0 + ty + 8*r, k = k0 + tx;
        float f = t[tx][ty + 8*r] / s[n];
        int8_t h8, l8;
        split_i8(f, h8, l8);
        T1[(size_t)n * K + k] = h8;
        T0[(size_t)n * K + k] = l8;
    }
}
// activation row quant: A[M][K] fp32 -> Q1,Q0 int8 + s[row]
__global__ __launch_bounds__(256) void aquant(const float* __restrict__ A,
                                              int8_t* __restrict__ Q1, int8_t* __restrict__ Q0,
                                              float* __restrict__ s, int K)
{
    __shared__ float red[8];
    const int row = blockIdx.x, tid = threadIdx.x;
    const float* rp = A + (size_t)row * K;
    float m = 0.f;
    for (int c = tid * 4; c < K; c += 1024) {
        float4 v = *(const float4*)(rp + c);
        m = fmaxf(m, fmaxf(fmaxf(fabsf(v.x), fabsf(v.y)), fmaxf(fabsf(v.z), fabsf(v.w))));
    }
#pragma unroll
    for (int off = 16; off; off >>= 1) m = fmaxf(m, __shfl_xor_sync(0xffffffffu, m, off));
    if ((tid & 31) == 0) red[tid >> 5] = m;
    __syncthreads();
    float tot = red[0];
#pragma unroll
    for (int i = 1; i < 8; i++) tot = fmaxf(tot, red[i]);
    const float sc = fmaxf(tot, 1e-20f) * (1.0f / 16256.0f);
    if (tid == 0) s[row] = sc;
    const float is = 1.0f / sc;
    for (int c = tid * 4; c < K; c += 1024) {
        float4 v = *(const float4*)(rp + c);
        int8_t h0,l0,h1,l1,h2,l2,h3,l3;
        split_i8(v.x * is, h0, l0);
        split_i8(v.y * is, h1, l1);
        split_i8(v.z * is, h2, l2);
        split_i8(v.w * is, h3, l3);
        *(char4*)(Q1 + (size_t)row * K + c) = make_char4(h0, h1, h2, h3);
        *(char4*)(Q0 + (size_t)row * K + c) = make_char4(l0, l1, l2, l3);
    }
}

// ---------------- int8x3 IMMA GEMM: C[M,N] = (sa.(128A1+A0)) @ (sb.(128B1+B0))^T ----------------
// Block 128x128, BK=64, 8 warps (2m x 4n), warp tile 64x32.
// smem: A1/A0/B1/B0 each [128 rows][64 int8] pad to 80B = 10240B; double buffered.
// EPI 1: bf16 hi/lo split to g_qkv* (q scaled 1/8)   EPI 2: +bias+res   EPI 3: relu(+bias)
#define IS_BUF   40960
#define SMEM_I   (2*IS_BUF)

template<int EPI>
__global__ __launch_bounds__(256, 1)
void i8_gemm(const int8_t* __restrict__ A1g, const int8_t* __restrict__ A0g,
             const float* __restrict__ sa,
             const int8_t* __restrict__ B1g, const int8_t* __restrict__ B0g,
             const float* __restrict__ sb,
             float* __restrict__ C, const float* __restrict__ bias,
             const float* __restrict__ res, int N, int K,
             __nv_bfloat16* __restrict__ Ohi, __nv_bfloat16* __restrict__ Olo)
{
    extern __shared__ char smem[];
    const uint32_t sbase = smem_u32(smem);
    const int tid = threadIdx.x, wid = tid >> 5, lane = tid & 31;
    const int g = lane >> 2, t = lane & 3;
    const int wm = wid >> 2, wn = wid & 3;
    const int bm = blockIdx.y, bn = blockIdx.x;

    int hi[4][4][4], mid[4][4][4];
#pragma unroll
    for (int mt = 0; mt < 4; mt++)
#pragma unroll
        for (int nt = 0; nt < 4; nt++)
#pragma unroll
            for (int f = 0; f < 4; f++) { hi[mt][nt][f] = 0; mid[mt][nt][f] = 0; }

    auto cp_all = [&](int buf, int kb) {
#pragma unroll
        for (int j = 0; j < 8; j++) {
            const int cidx = tid + 256 * j;
            const int arr = cidx >> 9;      // 0:A1 1:A0 2:B1 3:B0
            const int cc  = cidx & 511;
            const int row = cc >> 2, kc = cc & 3;
            const int8_t* gp = (arr == 0 ? A1g : arr == 1 ? A0g : arr == 2 ? B1g : B0g);
            const int base = (arr < 2 ? bm : bn) * 128;
            const int8_t* src = gp + (size_t)(base + row) * K + kb * 64 + kc * 16;
            const uint32_t dst = sbase + buf * IS_BUF + arr * 10240 + row * 80 + kc * 16;
            asm volatile("cp.async.cg.shared.global [%0], [%1], 16;\n" :: "r"(dst), "l"(src));
        }
        asm volatile("cp.async.commit_group;\n");
    };

    const uint32_t a_off = (uint32_t)((wm * 64 + (lane & 15)) * 80 + ((lane >> 4) << 4));
    const uint32_t b_off = (uint32_t)((wn * 32 + ((lane >> 4) << 3) + (lane & 7)) * 80
                                      + (((lane >> 3) & 1) << 4));

    const int niter = K >> 6;
    cp_all(0, 0);
    asm volatile("cp.async.wait_group 0;\n");
    __syncthreads();

    for (int it = 0; it < niter; it++) {
        const int buf = it & 1;
        if (it + 1 < niter) cp_all(buf ^ 1, (it + 1));

        const uint32_t sb_ = sbase + buf * IS_BUF;
#pragma unroll
        for (int ks = 0; ks < 2; ks++) {
            uint32_t A1f[4][4], A0f[4][4], B1f[2][4], B0f[2][4];
#pragma unroll
            for (int mt = 0; mt < 4; mt++) {
                const uint32_t aa = sb_ + a_off + mt * (16 * 80) + ks * 32;
                ldsm4(A1f[mt], aa);
                ldsm4(A0f[mt], aa + 10240);
            }
#pragma unroll
            for (int ng = 0; ng < 2; ng++) {
                const uint32_t ba = sb_ + b_off + ng * (16 * 80) + ks * 32;
                ldsm4(B1f[ng], ba + 20480);
                ldsm4(B0f[ng], ba + 30720);
            }
#pragma unroll
            for (int mt = 0; mt < 4; mt++)
#pragma unroll
                for (int nt = 0; nt < 4; nt++) {
                    const uint32_t* b1 = &B1f[nt >> 1][(nt & 1) * 2];
                    const uint32_t* b0 = &B0f[nt >> 1][(nt & 1) * 2];
                    mma_s8(hi[mt][nt],  A1f[mt], b1);   // 16384 term
                    mma_s8(mid[mt][nt], A1f[mt], b0);   // 128 term
                    mma_s8(mid[mt][nt], A0f[mt], b1);   // 128 term
                }
        }

        if (it + 1 < niter) asm volatile("cp.async.wait_group 0;\n");
        __syncthreads();
    }

    // ---------------- epilogue ----------------
#pragma unroll
    for (int mt = 0; mt < 4; mt++) {
        const int r0 = bm * 128 + wm * 64 + mt * 16 + g;
        const float sar[2] = { sa[r0], sa[r0 + 8] };
#pragma unroll
        for (int nt = 0; nt < 4; nt++) {
            const int c0 = bn * 128 + wn * 32 + nt * 8 + t * 2;
            const float sbc[2] = { sb[c0], sb[c0 + 1] };
#pragma unroll
            for (int half = 0; half < 2; half++) {
                const int r = r0 + half * 8;
                float v0 = sar[half] * sbc[0] *
                    fmaf(16384.f, (float)hi[mt][nt][half*2],   128.f * (float)mid[mt][nt][half*2]);
                float v1 = sar[half] * sbc[1] *
                    fmaf(16384.f, (float)hi[mt][nt][half*2+1], 128.f * (float)mid[mt][nt][half*2+1]);
                if (EPI == 1) {
                    const int which = c0 >> 10, cm = c0 & 1023;
                    if (which == 0) { v0 *= 0.125f; v1 *= 0.125f; }
                    __nv_bfloat16 h0 = __float2bfloat16(v0), h1 = __float2bfloat16(v1);
                    __nv_bfloat16 l0 = __float2bfloat16(v0 - __bfloat162float(h0));
                    __nv_bfloat16 l1 = __float2bfloat16(v1 - __bfloat162float(h1));
                    const size_t idx = (size_t)which * (NTOK * D_MODEL)
                        + (((size_t)((r >> 11) * NHEADS + (cm >> 6)) * SEQ + (r & 2047)) * DK + (cm & 63));
                    *(uint32_t*)(Ohi + idx) = packbf16pair(h0, h1);
                    *(uint32_t*)(Olo + idx) = packbf16pair(l0, l1);
                } else if (EPI == 2) {
                    const float* rs = res + (size_t)r * N + c0;
                    C[(size_t)r * N + c0]     = v0 + bias[c0]     + rs[0];
                    C[(size_t)r * N + c0 + 1] = v1 + bias[c0 + 1] + rs[1];
                } else {
                    float a0 = v0 + bias[c0],     a1 = v1 + bias[c0 + 1];
                    C[(size_t)r * N + c0]     = a0 > 0.f ? a0 : 0.f;
                    C[(size_t)r * N + c0 + 1] = a1 > 0.f ? a1 : 0.f;
                }
            }
        }
    }
}

// ---------------- FA2-style tensor-core attention (unchanged, proven) ----------------
#define AQ_H   0
#define AQ_L   18432
#define AKV    36864
#define AKVBUF 36864
#define ATSMEM (36864 + 2*36864)

__global__ __launch_bounds__(256, 2)
void attn_mma(const __nv_bfloat16* __restrict__ qkvh, const __nv_bfloat16* __restrict__ qkvl,
              const int* __restrict__ mask, float* __restrict__ ctx)
{
    extern __shared__ char sm[];
    const uint32_t sb = smem_u32(sm);
    const int tid = threadIdx.x, w = tid >> 5, lane = tid & 31;
    const int g = lane >> 2, t = lane & 3;
    const int qb = blockIdx.x, h = blockIdx.y, b = blockIdx.z;
    const size_t hoff = ((size_t)(b * NHEADS + h)) * SEQ * DK;

    const __nv_bfloat16* qh = qkvh + hoff + (size_t)qb * 128 * DK;
    const __nv_bfloat16* ql = qkvl + hoff + (size_t)qb * 128 * DK;
    const __nv_bfloat16* kh = qkvh + (size_t)NTOK * D_MODEL + hoff;
    const __nv_bfloat16* kl = qkvl + (size_t)NTOK * D_MODEL + hoff;
    const __nv_bfloat16* vh = qkvh + (size_t)2 * NTOK * D_MODEL + hoff;
    const __nv_bfloat16* vl = qkvl + (size_t)2 * NTOK * D_MODEL + hoff;

#pragma unroll
    for (int j = 0; j < 8; j++) {
        const int cidx = tid + j * 256;
        const int arr = cidx >> 10, cc = cidx & 1023;
        const int row = cc >> 3, k8 = cc & 7;
        const __nv_bfloat16* src = (arr == 0 ? qh : ql) + row * DK + k8 * 8;
        *(uint4*)(sm + AQ_H + arr * 18432 + row * 144 + k8 * 16) = *(const uint4*)src;
    }

    auto prefetch_kv = [&](int buf, int kv0) {
#pragma unroll
        for (int j = 0; j < 8; j++) {
            const int cidx = tid + j * 256;
            const int arr = cidx >> 9, cc = cidx & 511;
            const int row = cc >> 3, k8 = cc & 7;
            const __nv_bfloat16* src =
                (arr == 0 ? kh : arr == 1 ? kl : arr == 2 ? vh : vl)
                + (size_t)(kv0 + row) * DK + k8 * 8;
            const uint32_t dst = sb + AKV + buf * AKVBUF + arr * 9216 + row * 144 + k8 * 16;
            asm volatile("cp.async.cg.shared.global [%0], [%1], 16;\n" :: "r"(dst), "l"(src));
        }
        asm volatile("cp.async.commit_group;\n");
    };

    prefetch_kv(0, 0);

    float m0 = -1e30f, m1 = -1e30f, l0 = 0.f, l1 = 0.f;
    float co[8][4];
#pragma unroll
    for (int nt = 0; nt < 8; nt++)
#pragma unroll
        for (int f = 0; f < 4; f++) co[nt][f] = 0.f;

    const uint32_t qa_off = (uint32_t)((w * 16 + (lane & 15)) * 144 + ((lane >> 4) << 4));
    const uint32_t kb_sub = (uint32_t)((((lane >> 4) << 3) + (lane & 7)) * 144
                                       + (((lane >> 3) & 1) << 4));
    const uint32_t vb_sub = (uint32_t)(((((lane >> 3) & 1) << 3) + (lane & 7)) * 144
                                       + ((lane >> 4) << 4));
    const int* mrow_base = mask + b * SEQ;

    for (int it = 0; it < SEQ / 64; it++) {
        const int buf = it & 1;
        const int kv0 = it * 64;
        asm volatile("cp.async.wait_group 0;\n");
        __syncthreads();
        if (it + 1 < SEQ / 64) prefetch_kv(buf ^ 1, kv0 + 64);

        const uint32_t kvb = sb + AKV + buf * AKVBUF;

        float cs[8][4];
#pragma unroll
        for (int nt = 0; nt < 8; nt++)
#pragma unroll
            for (int f = 0; f < 4; f++) cs[nt][f] = 0.f;
#pragma unroll
        for (int ks = 0; ks < 4; ks++) {
            uint32_t Qh_[4], Ql_[4];
            const uint32_t aa = sb + qa_off + ks * 32;
            ldsm4(Qh_, aa + AQ_H);
            ldsm4(Ql_, aa + AQ_L);
#pragma unroll
            for (int ng = 0; ng < 4; ng++) {
                uint32_t Kh_[4], Kl_[4];
                const uint32_t ba = kvb + ng * (16 * 144) + kb_sub + ks * 32;
                ldsm4(Kh_, ba);
                ldsm4(Kl_, ba + 9216);
#pragma unroll
                for (int h2 = 0; h2 < 2; h2++) {
                    const int nt = ng * 2 + h2;
                    mma_bf16(cs[nt], Qh_, &Kh_[h2 * 2]);
                    mma_bf16(cs[nt], Qh_, &Kl_[h2 * 2]);
                    mma_bf16(cs[nt], Ql_, &Kh_[h2 * 2]);
                }
            }
        }

#pragma unroll
        for (int nt = 0; nt < 8; nt++) {
            int2 mv = *(const int2*)(mrow_base + kv0 + nt * 8 + t * 2);
            if (mv.x == 0) { cs[nt][0] = -1e9f; cs[nt][2] = -1e9f; }
            if (mv.y == 0) { cs[nt][1] = -1e9f; cs[nt][3] = -1e9f; }
        }
        float mx0 = cs[0][0], mx1 = cs[0][2];
#pragma unroll
        for (int nt = 0; nt < 8; nt++) {
            mx0 = fmaxf(mx0, fmaxf(cs[nt][0], cs[nt][1]));
            mx1 = fmaxf(mx1, fmaxf(cs[nt][2], cs[nt][3]));
        }
        mx0 = fmaxf(mx0, __shfl_xor_sync(0xffffffffu, mx0, 1));
        mx0 = fmaxf(mx0, __shfl_xor_sync(0xffffffffu, mx0, 2));
        mx1 = fmaxf(mx1, __shfl_xor_sync(0xffffffffu, mx1, 1));
        mx1 = fmaxf(mx1, __shfl_xor_sync(0xffffffffu, mx1, 2));
        const float mn0 = fmaxf(m0, mx0), mn1 = fmaxf(m1, mx1);
        const float f0 = fexp(m0 - mn0), f1 = fexp(m1 - mn1);
        m0 = mn0; m1 = mn1;

        uint32_t phg[8], phg8[8], plg[8], plg8[8];
        float rs0 = 0.f, rs1 = 0.f;
#pragma unroll
        for (int nt = 0; nt < 8; nt++) {
            float p0 = fexp(cs[nt][0] - mn0);
            float p1 = fexp(cs[nt][1] - mn0);
            float p2 = fexp(cs[nt][2] - mn1);
            float p3 = fexp(cs[nt][3] - mn1);
            rs0 += p0 + p1; rs1 += p2 + p3;
            __nv_bfloat16 h0 = __float2bfloat16(p0), h1 = __float2bfloat16(p1);
            __nv_bfloat16 h2 = __float2bfloat16(p2), h3 = __float2bfloat16(p3);
            phg[nt]  = packbf16pair(h0, h1);
            phg8[nt] = packbf16pair(h2, h3);
            plg[nt]  = packbf2(p0 - __bfloat162float(h0), p1 - __bfloat162float(h1));
            plg8[nt] = packbf2(p2 - __bfloat162float(h2), p3 - __bfloat162float(h3));
        }
        rs0 += __shfl_xor_sync(0xffffffffu, rs0, 1);
        rs0 += __shfl_xor_sync(0xffffffffu, rs0, 2);
        rs1 += __shfl_xor_sync(0xffffffffu, rs1, 1);
        rs1 += __shfl_xor_sync(0xffffffffu, rs1, 2);
        l0 = l0 * f0 + rs0;
        l1 = l1 * f1 + rs1;

#pragma unroll
        for (int nt = 0; nt < 8; nt++) {
            co[nt][0] *= f0; co[nt][1] *= f0;
            co[nt][2] *= f1; co[nt][3] *= f1;
        }

#pragma unroll
        for (int kc = 0; kc < 4; kc++) {
            uint32_t Ah[4] = { phg[2*kc], phg8[2*kc], phg[2*kc+1], phg8[2*kc+1] };
            uint32_t Al[4] = { plg[2*kc], plg8[2*kc], plg[2*kc+1], plg8[2*kc+1] };
#pragma unroll
            for (int ng = 0; ng < 4; ng++) {
                uint32_t Vh_[4], Vl_[4];
                const uint32_t va = kvb + 18432 + kc * (16 * 144) + vb_sub + ng * 32;
                ldsm4t(Vh_, va);
                ldsm4t(Vl_, va + 9216);
#pragma unroll
                for (int h2 = 0; h2 < 2; h2++) {
                    const int nt = ng * 2 + h2;
                    mma_bf16(co[nt], Ah, &Vh_[h2 * 2]);
                    mma_bf16(co[nt], Ah, &Vl_[h2 * 2]);
                    mma_bf16(co[nt], Al, &Vh_[h2 * 2]);
                }
            }
        }
    }

    const float inv0 = 1.0f / l0, inv1 = 1.0f / l1;
    const int r0 = qb * 128 + w * 16 + g;
    float* dst0 = ctx + ((size_t)(b * SEQ + r0)) * D_MODEL + h * 64;
    float* dst1 = ctx + ((size_t)(b * SEQ + r0 + 8)) * D_MODEL + h * 64;
#pragma unroll
    for (int nt = 0; nt < 8; nt++) {
        const int col = nt * 8 + t * 2;
        *(float2*)(dst0 + col) = make_float2(co[nt][0] * inv0, co[nt][1] * inv0);
        *(float2*)(dst1 + col) = make_float2(co[nt][2] * inv1, co[nt][3] * inv1);
    }
}

// ---------------- LayerNorm (ddof=1, eps added to std) ----------------
__device__ __forceinline__ float warp_sum(float s) {
#pragma unroll
    for (int off = 16; off; off >>= 1) s += __shfl_xor_sync(0xffffffffu, s, off);
    return s;
}

__global__ __launch_bounds__(256)
void ln_kernel(const float* __restrict__ in, const float* __restrict__ alpha,
               const float* __restrict__ beta, float* __restrict__ out)
{
    __shared__ float red[8];
    const int row = blockIdx.x, tid = threadIdx.x;
    const float* rp = in + (size_t)row * D_MODEL;
    float4 v = *(const float4*)(rp + tid*4);

    float s = v.x + v.y + v.z + v.w;
    s = warp_sum(s);
    if ((tid & 31) == 0) red[tid >> 5] = s;
    __syncthreads();
    float tot = 0.f;
#pragma unroll
    for (int i = 0; i < 8; i++) tot += red[i];
    float mean = tot * (1.0f / 1024.0f);

    float dx = v.x - mean, dy = v.y - mean, dz = v.z - mean, dw = v.w - mean;
    float sq = dx*dx + dy*dy + dz*dz + dw*dw;
    __syncthreads();
    sq = warp_sum(sq);
    if ((tid & 31) == 0) red[tid >> 5] = sq;
    __syncthreads();
    float tot2 = 0.f;
#pragma unroll
    for (int i = 0; i < 8; i++) tot2 += red[i];
    float var  = tot2 * (1.0f / 1023.0f);
    float rstd = 1.0f / (sqrtf(var) + 1e-6f);

    float4 a = *(const float4*)(alpha + tid*4);
    float4 bb = *(const float4*)(beta + tid*4);
    float4 o;
    o.x = a.x * dx * rstd + bb.x;
    o.y = a.y * dy * rstd + bb.y;
    o.z = a.z * dz * rstd + bb.z;
    o.w = a.w * dw * rstd + bb.w;
    *(float4*)(out + (size_t)row * D_MODEL + tid*4) = o;
}

// ---------------- host ----------------
extern "C" void kernel_launch(void* const* d_in, const int* in_sizes, int n_in,
                              void* d_out, int out_size)
{
    const float* x      = (const float*)d_in[0];
    const int*   mask   = (const int*)  d_in[1];
    const float* wq     = (const float*)d_in[2];
    const float* wk     = (const float*)d_in[3];
    const float* wv     = (const float*)d_in[4];
    const float* wo     = (const float*)d_in[5];
    const float* wo_b   = (const float*)d_in[6];
    const float* w1     = (const float*)d_in[7];
    const float* b1     = (const float*)d_in[8];
    const float* w2     = (const float*)d_in[9];
    const float* b2     = (const float*)d_in[10];
    const float* alpha1 = (const float*)d_in[11];
    const float* bias1  = (const float*)d_in[12];
    const float* alpha2 = (const float*)d_in[13];
    const float* bias2  = (const float*)d_in[14];
    float* out = (float*)d_out;

    float *ctx, *s1, *x1, *ff, *s2;
    __nv_bfloat16 *qkvh, *qkvl;
    int8_t *xq1,*xq0,*cq1,*cq0,*x1q1,*x1q0,*ffq1,*ffq0;
    float *sx,*sctx,*sx1,*sff;
    int8_t *wqkv1,*wqkv0,*wo1,*wo0,*w11,*w10,*w21,*w20;
    float *swqkv,*swo,*sw1,*sw2;
    cudaGetSymbolAddress((void**)&ctx, g_ctx);
    cudaGetSymbolAddress((void**)&s1,  g_s1);
    cudaGetSymbolAddress((void**)&x1,  g_x1);
    cudaGetSymbolAddress((void**)&ff,  g_ff);
    cudaGetSymbolAddress((void**)&s2,  g_s2);
    cudaGetSymbolAddress((void**)&qkvh, g_qkvh);
    cudaGetSymbolAddress((void**)&qkvl, g_qkvl);
    cudaGetSymbolAddress((void**)&xq1, g_xq1);   cudaGetSymbolAddress((void**)&xq0, g_xq0);
    cudaGetSymbolAddress((void**)&cq1, g_cq1);   cudaGetSymbolAddress((void**)&cq0, g_cq0);
    cudaGetSymbolAddress((void**)&x1q1, g_x1q1); cudaGetSymbolAddress((void**)&x1q0, g_x1q0);
    cudaGetSymbolAddress((void**)&ffq1, g_ffq1); cudaGetSymbolAddress((void**)&ffq0, g_ffq0);
    cudaGetSymbolAddress((void**)&sx, g_sx);     cudaGetSymbolAddress((void**)&sctx, g_sctx);
    cudaGetSymbolAddress((void**)&sx1, g_sx1);   cudaGetSymbolAddress((void**)&sff, g_sff);
    cudaGetSymbolAddress((void**)&wqkv1, g_wqkv1); cudaGetSymbolAddress((void**)&wqkv0, g_wqkv0);
    cudaGetSymbolAddress((void**)&wo1, g_wo1);     cudaGetSymbolAddress((void**)&wo0, g_wo0);
    cudaGetSymbolAddress((void**)&w11, g_w11);     cudaGetSymbolAddress((void**)&w10, g_w10);
    cudaGetSymbolAddress((void**)&w21, g_w21);     cudaGetSymbolAddress((void**)&w20, g_w20);
    cudaGetSymbolAddress((void**)&swqkv, g_swqkv); cudaGetSymbolAddress((void**)&swo, g_swo);
    cudaGetSymbolAddress((void**)&sw1, g_sw1);     cudaGetSymbolAddress((void**)&sw2, g_sw2);

    cudaFuncSetAttribute(i8_gemm<1>, cudaFuncAttributeMaxDynamicSharedMemorySize, SMEM_I);
    cudaFuncSetAttribute(i8_gemm<2>, cudaFuncAttributeMaxDynamicSharedMemorySize, SMEM_I);
    cudaFuncSetAttribute(i8_gemm<3>, cudaFuncAttributeMaxDynamicSharedMemorySize, SMEM_I);
    cudaFuncSetAttribute(attn_mma,   cudaFuncAttributeMaxDynamicSharedMemorySize, ATSMEM);

    dim3 tblk(32, 8);
    // weight prep: per-column scales then transposed int8 hi/lo
    wcolmax<<<4, 256>>>(wq, swqkv, D_MODEL, D_MODEL);
    wcolmax<<<4, 256>>>(wk, swqkv + D_MODEL, D_MODEL, D_MODEL);
    wcolmax<<<4, 256>>>(wv, swqkv + 2*D_MODEL, D_MODEL, D_MODEL);
    wcolmax<<<4, 256>>>(wo, swo, D_MODEL, D_MODEL);
    wcolmax<<<16, 256>>>(w1, sw1, D_MODEL, DFF);
    wcolmax<<<4, 256>>>(w2, sw2, DFF, D_MODEL);
    wquant<<<dim3(32, 32), tblk>>>(wq, swqkv,             wqkv1,                     wqkv0,                     D_MODEL, D_MODEL);
    wquant<<<dim3(32, 32), tblk>>>(wk, swqkv + D_MODEL,   wqkv1 + D_MODEL*D_MODEL,   wqkv0 + D_MODEL*D_MODEL,   D_MODEL, D_MODEL);
    wquant<<<dim3(32, 32), tblk>>>(wv, swqkv + 2*D_MODEL, wqkv1 + 2*D_MODEL*D_MODEL, wqkv0 + 2*D_MODEL*D_MODEL, D_MODEL, D_MODEL);
    wquant<<<dim3(32, 32), tblk>>>(wo, swo, wo1, wo0, D_MODEL, D_MODEL);
    wquant<<<dim3(128, 32), tblk>>>(w1, sw1, w11, w10, D_MODEL, DFF);
    wquant<<<dim3(32, 128), tblk>>>(w2, sw2, w21, w20, DFF, D_MODEL);

    // QKV: quant x then fused int8 GEMM (N=3072) -> bf16 hi/lo head-transposed
    aquant<<<NTOK, 256>>>(x, xq1, xq0, sx, D_MODEL);
    i8_gemm<1><<<dim3(24, 32), 256, SMEM_I>>>(xq1, xq0, sx, wqkv1, wqkv0, swqkv,
                                              nullptr, nullptr, nullptr, 3*D_MODEL, D_MODEL, qkvh, qkvl);

    attn_mma<<<dim3(SEQ/128, NHEADS, BATCH), 256, ATSMEM>>>(qkvh, qkvl, mask, ctx);

    // O projection + residual, LN1
    aquant<<<NTOK, 256>>>(ctx, cq1, cq0, sctx, D_MODEL);
    i8_gemm<2><<<dim3(8, 32), 256, SMEM_I>>>(cq1, cq0, sctx, wo1, wo0, swo,
                                             s1, wo_b, x, D_MODEL, D_MODEL, nullptr, nullptr);
    ln_kernel<<<NTOK, 256>>>(s1, alpha1, bias1, x1);

    // FFN
    aquant<<<NTOK, 256>>>(x1, x1q1, x1q0, sx1, D_MODEL);
    i8_gemm<3><<<dim3(32, 32), 256, SMEM_I>>>(x1q1, x1q0, sx1, w11, w10, sw1,
                                              ff, b1, nullptr, DFF, D_MODEL, nullptr, nullptr);
    aquant<<<NTOK, 256>>>(ff, ffq1, ffq0, sff, DFF);
    i8_gemm<2><<<dim3(8, 32), 256, SMEM_I>>>(ffq1, ffq0, sff, w21, w20, sw2,
                                             s2, b2, x1, D_MODEL, DFF, nullptr, nullptr);
    ln_kernel<<<NTOK, 256>>>(s2, alpha2, bias2, out);
}

// round 12
// speedup vs baseline: 3.8003x; 3.8003x over previous
#include <cuda_runtime.h>
#include <cuda_bf16.h>
#include <math.h>
#include <stdint.h>

#define D_MODEL 1024
#define NHEADS  16
#define DK      64
#define SEQ     2048
#define BATCH   2
#define NTOK    (BATCH*SEQ)   // 4096
#define DFF     4096

// ---------------- scratch (no allocations allowed) ----------------
__device__ float g_s1 [NTOK*D_MODEL];
__device__ float g_x1 [NTOK*D_MODEL];
__device__ float g_s2 [NTOK*D_MODEL];

// bf16 hi/lo operand arrays
__device__ __nv_bfloat16 g_xh  [NTOK*D_MODEL];   __device__ __nv_bfloat16 g_xl  [NTOK*D_MODEL];
__device__ __nv_bfloat16 g_qkvh[3*NTOK*D_MODEL]; __device__ __nv_bfloat16 g_qkvl[3*NTOK*D_MODEL];
__device__ __nv_bfloat16 g_ctxh[NTOK*D_MODEL];   __device__ __nv_bfloat16 g_ctxl[NTOK*D_MODEL];
__device__ __nv_bfloat16 g_x1h [NTOK*D_MODEL];   __device__ __nv_bfloat16 g_x1l [NTOK*D_MODEL];
__device__ __nv_bfloat16 g_ffh [NTOK*DFF];       __device__ __nv_bfloat16 g_ffl [NTOK*DFF];

// pre-split transposed weights [N][K], bf16 hi/lo
__device__ __nv_bfloat16 g_wqkv_hi[3*D_MODEL*D_MODEL];
__device__ __nv_bfloat16 g_wqkv_lo[3*D_MODEL*D_MODEL];
__device__ __nv_bfloat16 g_wo_hi  [D_MODEL*D_MODEL];
__device__ __nv_bfloat16 g_wo_lo  [D_MODEL*D_MODEL];
__device__ __nv_bfloat16 g_w1_hi  [DFF*D_MODEL];
__device__ __nv_bfloat16 g_w1_lo  [DFF*D_MODEL];
__device__ __nv_bfloat16 g_w2_hi  [D_MODEL*DFF];
__device__ __nv_bfloat16 g_w2_lo  [D_MODEL*DFF];

// ---------------- helpers ----------------
__device__ __forceinline__ uint32_t smem_u32(const void* p) {
    uint32_t a;
    asm("{ .reg .u64 t; cvta.to.shared.u64 t, %1; cvt.u32.u64 %0, t; }" : "=r"(a) : "l"(p));
    return a;
}
__device__ __forceinline__ void ldsm4(uint32_t* r, uint32_t addr) {
    asm volatile("ldmatrix.sync.aligned.m8n8.x4.shared.b16 {%0,%1,%2,%3}, [%4];"
        : "=r"(r[0]), "=r"(r[1]), "=r"(r[2]), "=r"(r[3]) : "r"(addr));
}
__device__ __forceinline__ void ldsm4t(uint32_t* r, uint32_t addr) {
    asm volatile("ldmatrix.sync.aligned.m8n8.x4.trans.shared.b16 {%0,%1,%2,%3}, [%4];"
        : "=r"(r[0]), "=r"(r[1]), "=r"(r[2]), "=r"(r[3]) : "r"(addr));
}
__device__ __forceinline__ void mma_bf16(float* d, const uint32_t* a, const uint32_t* b) {
    asm volatile(
        "mma.sync.aligned.m16n8k16.row.col.f32.bf16.bf16.f32 "
        "{%0,%1,%2,%3}, {%4,%5,%6,%7}, {%8,%9}, {%0,%1,%2,%3};"
        : "+f"(d[0]), "+f"(d[1]), "+f"(d[2]), "+f"(d[3])
        : "r"(a[0]), "r"(a[1]), "r"(a[2]), "r"(a[3]), "r"(b[0]), "r"(b[1]));
}
__device__ __forceinline__ uint32_t packbf2(float x, float y) {
    __nv_bfloat162 h = __floats2bfloat162_rn(x, y);
    return *(uint32_t*)&h;
}
__device__ __forceinline__ uint32_t packbf16pair(__nv_bfloat16 a, __nv_bfloat16 b) {
    return (uint32_t)__bfloat16_as_ushort(a) | ((uint32_t)__bfloat16_as_ushort(b) << 16);
}
__device__ __forceinline__ float fexp(float x) {
    float y = x * 1.4426950408889634f;
    y = fmaxf(y, -126.0f);
    float t = y + 12582912.0f;
    int   n = __float_as_int(t) - 0x4B400000;
    float f = y - (t - 12582912.0f);
    float p = 1.3333558146428443e-3f;
    p = fmaf(p, f, 9.6181291076284772e-3f);
    p = fmaf(p, f, 5.5504108664821580e-2f);
    p = fmaf(p, f, 2.4022650695910072e-1f);
    p = fmaf(p, f, 6.9314718055994531e-1f);
    p = fmaf(p, f, 1.0f);
    return __int_as_float(__float_as_int(p) + (n << 23));
}
// write fp32 pair as hi/lo bf16 pairs
__device__ __forceinline__ void split_pair(float v0, float v1, uint32_t& hp, uint32_t& lp) {
    __nv_bfloat16 h0 = __float2bfloat16(v0), h1 = __float2bfloat16(v1);
    hp = packbf16pair(h0, h1);
    lp = packbf2(v0 - __bfloat162float(h0), v1 - __bfloat162float(h1));
}

// ---------------- elementwise fp32 -> bf16 hi/lo split ----------------
__global__ __launch_bounds__(256)
void xsplit(const float* __restrict__ A, __nv_bfloat16* __restrict__ H,
            __nv_bfloat16* __restrict__ L)
{
    const size_t i = ((size_t)blockIdx.x * 256 + threadIdx.x) * 4;
    float4 v = *(const float4*)(A + i);
    uint32_t h0, l0, h1, l1;
    split_pair(v.x, v.y, h0, l0);
    split_pair(v.z, v.w, h1, l1);
    *(uint2*)(H + i) = make_uint2(h0, h1);
    *(uint2*)(L + i) = make_uint2(l0, l1);
}

// ---------------- weight prep: W[K][N] fp32 -> T[N][K] bf16 hi/lo ----------------
__global__ void prep_w(const float* __restrict__ W, __nv_bfloat16* __restrict__ Thi,
                       __nv_bfloat16* __restrict__ Tlo, int K, int N)
{
    __shared__ float t[32][33];
    const int k0 = blockIdx.y * 32, n0 = blockIdx.x * 32;
    const int tx = threadIdx.x, ty = threadIdx.y;
#pragma unroll
    for (int r = 0; r < 4; r++)
        t[ty + 8*r][tx] = W[(size_t)(k0 + ty + 8*r) * N + n0 + tx];
    __syncthreads();
#pragma unroll
    for (int r = 0; r < 4; r++) {
        const int n = n0 + ty + 8*r, k = k0 + tx;
        float x = t[tx][ty + 8*r];
        __nv_bfloat16 hi = __float2bfloat16(x);
        __nv_bfloat16 lo = __float2bfloat16(x - __bfloat162float(hi));
        Thi[(size_t)n * K + k] = hi;
        Tlo[(size_t)n * K + k] = lo;
    }
}

// ---------------- bf16x3 mma.sync GEMM, all-cp.async operands ----------------
// C[M,N] = (Ahi+Alo)[M,K] @ (Bhi+Blo)[N,K]^T  via hh+hl+lh
// Block 128x128, BK=32, 8 warps (2m x 4n), warp tile 64x32.
// smem per buffer: Ah/Al/Bh/Bl each [128 rows][32 bf16] pad 80B = 10240B
// EPI 1: bf16 hi/lo split to g_qkv* head-transposed (q scaled 1/8)
// EPI 2: fp32 C = acc + bias + res
// EPI 3: bf16 hi/lo split of relu(acc + bias)
#define GS_BUF   40960
#define SMEM_G   (2*GS_BUF)

template<int EPI>
__global__ __launch_bounds__(256, 1)
void bf16_gemm(const __nv_bfloat16* __restrict__ Ahi, const __nv_bfloat16* __restrict__ Alo,
               const __nv_bfloat16* __restrict__ Bhi, const __nv_bfloat16* __restrict__ Blo,
               float* __restrict__ C, const float* __restrict__ bias,
               const float* __restrict__ res, int N, int K,
               __nv_bfloat16* __restrict__ Ohi, __nv_bfloat16* __restrict__ Olo)
{
    extern __shared__ char smem[];
    const uint32_t sbase = smem_u32(smem);
    const int tid = threadIdx.x, wid = tid >> 5, lane = tid & 31;
    const int g = lane >> 2, t = lane & 3;
    const int wm = wid >> 2, wn = wid & 3;
    const int bm = blockIdx.y, bn = blockIdx.x;

    float c[4][4][4];
#pragma unroll
    for (int mt = 0; mt < 4; mt++)
#pragma unroll
        for (int nt = 0; nt < 4; nt++)
#pragma unroll
            for (int f = 0; f < 4; f++) c[mt][nt][f] = 0.f;

    auto cp_all = [&](int buf, int kb) {
#pragma unroll
        for (int j = 0; j < 8; j++) {
            const int cidx = tid + 256 * j;
            const int arr = cidx >> 9;      // 0:Ah 1:Al 2:Bh 3:Bl
            const int cc  = cidx & 511;
            const int row = cc >> 2, kc = cc & 3;
            const __nv_bfloat16* gp = (arr == 0 ? Ahi : arr == 1 ? Alo : arr == 2 ? Bhi : Blo);
            const int base = (arr < 2 ? bm : bn) * 128;
            const __nv_bfloat16* src = gp + (size_t)(base + row) * K + kb * 32 + kc * 8;
            const uint32_t dst = sbase + buf * GS_BUF + arr * 10240 + row * 80 + kc * 16;
            asm volatile("cp.async.cg.shared.global [%0], [%1], 16;\n" :: "r"(dst), "l"(src));
        }
        asm volatile("cp.async.commit_group;\n");
    };

    const uint32_t a_off = (uint32_t)((wm * 64 + (lane & 15)) * 80 + ((lane >> 4) << 4));
    const uint32_t b_off = (uint32_t)((wn * 32 + ((lane >> 4) << 3) + (lane & 7)) * 80
                                      + (((lane >> 3) & 1) << 4));

    const int niter = K >> 5;
    cp_all(0, 0);
    asm volatile("cp.async.wait_group 0;\n");
    __syncthreads();

    for (int it = 0; it < niter; it++) {
        const int buf = it & 1;
        if (it + 1 < niter) cp_all(buf ^ 1, it + 1);

        const uint32_t sb = sbase + buf * GS_BUF;
#pragma unroll
        for (int ks = 0; ks < 2; ks++) {
            uint32_t Ah[4][4], Al[4][4], Bh[2][4], Bl[2][4];
#pragma unroll
            for (int mt = 0; mt < 4; mt++) {
                const uint32_t aa = sb + a_off + mt * (16 * 80) + ks * 32;
                ldsm4(Ah[mt], aa);
                ldsm4(Al[mt], aa + 10240);
            }
#pragma unroll
            for (int ng = 0; ng < 2; ng++) {
                const uint32_t ba = sb + b_off + ng * (16 * 80) + ks * 32;
                ldsm4(Bh[ng], ba + 20480);
                ldsm4(Bl[ng], ba + 30720);
            }
#pragma unroll
            for (int mt = 0; mt < 4; mt++)
#pragma unroll
                for (int nt = 0; nt < 4; nt++) {
                    const uint32_t* bh = &Bh[nt >> 1][(nt & 1) * 2];
                    const uint32_t* bl = &Bl[nt >> 1][(nt & 1) * 2];
                    mma_bf16(c[mt][nt], Ah[mt], bh);   // hi*hi
                    mma_bf16(c[mt][nt], Ah[mt], bl);   // hi*lo
                    mma_bf16(c[mt][nt], Al[mt], bh);   // lo*hi
                }
        }

        if (it + 1 < niter) asm volatile("cp.async.wait_group 0;\n");
        __syncthreads();
    }

    // ---------------- epilogue ----------------
#pragma unroll
    for (int mt = 0; mt < 4; mt++) {
        const int r0 = bm * 128 + wm * 64 + mt * 16 + g;
#pragma unroll
        for (int nt = 0; nt < 4; nt++) {
            const int c0 = bn * 128 + wn * 32 + nt * 8 + t * 2;
#pragma unroll
            for (int half = 0; half < 2; half++) {
                const int r = r0 + half * 8;
                float v0 = c[mt][nt][half * 2], v1 = c[mt][nt][half * 2 + 1];
                if (EPI == 1) {
                    const int which = c0 >> 10, cm = c0 & 1023;
                    if (which == 0) { v0 *= 0.125f; v1 *= 0.125f; }
                    uint32_t hp, lp;
                    split_pair(v0, v1, hp, lp);
                    const size_t idx = (size_t)which * (NTOK * D_MODEL)
                        + (((size_t)((r >> 11) * NHEADS + (cm >> 6)) * SEQ + (r & 2047)) * DK + (cm & 63));
                    *(uint32_t*)(Ohi + idx) = hp;
                    *(uint32_t*)(Olo + idx) = lp;
                } else if (EPI == 2) {
                    const float* rs = res + (size_t)r * N + c0;
                    C[(size_t)r * N + c0]     = v0 + bias[c0]     + rs[0];
                    C[(size_t)r * N + c0 + 1] = v1 + bias[c0 + 1] + rs[1];
                } else { // 3: relu -> bf16 hi/lo
                    float a0 = fmaxf(v0 + bias[c0], 0.f);
                    float a1 = fmaxf(v1 + bias[c0 + 1], 0.f);
                    uint32_t hp, lp;
                    split_pair(a0, a1, hp, lp);
                    const size_t idx = (size_t)r * N + c0;
                    *(uint32_t*)(Ohi + idx) = hp;
                    *(uint32_t*)(Olo + idx) = lp;
                }
            }
        }
    }
}

// ---------------- FA2-style tensor-core attention (R10-proven; bf16 ctx out) ----------------
#define AQ_H   0
#define AQ_L   18432
#define AKV    36864
#define AKVBUF 36864
#define ATSMEM (36864 + 2*36864)

__global__ __launch_bounds__(256, 2)
void attn_mma(const __nv_bfloat16* __restrict__ qkvh, const __nv_bfloat16* __restrict__ qkvl,
              const int* __restrict__ mask,
              __nv_bfloat16* __restrict__ ctxh, __nv_bfloat16* __restrict__ ctxl)
{
    extern __shared__ char sm[];
    const uint32_t sb = smem_u32(sm);
    const int tid = threadIdx.x, w = tid >> 5, lane = tid & 31;
    const int g = lane >> 2, t = lane & 3;
    const int qb = blockIdx.x, h = blockIdx.y, b = blockIdx.z;
    const size_t hoff = ((size_t)(b * NHEADS + h)) * SEQ * DK;

    const __nv_bfloat16* qh = qkvh + hoff + (size_t)qb * 128 * DK;
    const __nv_bfloat16* ql = qkvl + hoff + (size_t)qb * 128 * DK;
    const __nv_bfloat16* kh = qkvh + (size_t)NTOK * D_MODEL + hoff;
    const __nv_bfloat16* kl = qkvl + (size_t)NTOK * D_MODEL + hoff;
    const __nv_bfloat16* vh = qkvh + (size_t)2 * NTOK * D_MODEL + hoff;
    const __nv_bfloat16* vl = qkvl + (size_t)2 * NTOK * D_MODEL + hoff;

#pragma unroll
    for (int j = 0; j < 8; j++) {
        const int cidx = tid + j * 256;
        const int arr = cidx >> 10, cc = cidx & 1023;
        const int row = cc >> 3, k8 = cc & 7;
        const __nv_bfloat16* src = (arr == 0 ? qh : ql) + row * DK + k8 * 8;
        *(uint4*)(sm + AQ_H + arr * 18432 + row * 144 + k8 * 16) = *(const uint4*)src;
    }

    auto prefetch_kv = [&](int buf, int kv0) {
#pragma unroll
        for (int j = 0; j < 8; j++) {
            const int cidx = tid + j * 256;
            const int arr = cidx >> 9, cc = cidx & 511;
            const int row = cc >> 3, k8 = cc & 7;
            const __nv_bfloat16* src =
                (arr == 0 ? kh : arr == 1 ? kl : arr == 2 ? vh : vl)
                + (size_t)(kv0 + row) * DK + k8 * 8;
            const uint32_t dst = sb + AKV + buf * AKVBUF + arr * 9216 + row * 144 + k8 * 16;
            asm volatile("cp.async.cg.shared.global [%0], [%1], 16;\n" :: "r"(dst), "l"(src));
        }
        asm volatile("cp.async.commit_group;\n");
    };

    prefetch_kv(0, 0);

    float m0 = -1e30f, m1 = -1e30f, l0 = 0.f, l1 = 0.f;
    float co[8][4];
#pragma unroll
    for (int nt = 0; nt < 8; nt++)
#pragma unroll
        for (int f = 0; f < 4; f++) co[nt][f] = 0.f;

    const uint32_t qa_off = (uint32_t)((w * 16 + (lane & 15)) * 144 + ((lane >> 4) << 4));
    const uint32_t kb_sub = (uint32_t)((((lane >> 4) << 3) + (lane & 7)) * 144
                                       + (((lane >> 3) & 1) << 4));
    const uint32_t vb_sub = (uint32_t)(((((lane >> 3) & 1) << 3) + (lane & 7)) * 144
                                       + ((lane >> 4) << 4));
    const int* mrow_base = mask + b * SEQ;

    for (int it = 0; it < SEQ / 64; it++) {
        const int buf = it & 1;
        const int kv0 = it * 64;
        asm volatile("cp.async.wait_group 0;\n");
        __syncthreads();
        if (it + 1 < SEQ / 64) prefetch_kv(buf ^ 1, kv0 + 64);

        const uint32_t kvb = sb + AKV + buf * AKVBUF;

        float cs[8][4];
#pragma unroll
        for (int nt = 0; nt < 8; nt++)
#pragma unroll
            for (int f = 0; f < 4; f++) cs[nt][f] = 0.f;
#pragma unroll
        for (int ks = 0; ks < 4; ks++) {
            uint32_t Qh_[4], Ql_[4];
            const uint32_t aa = sb + qa_off + ks * 32;
            ldsm4(Qh_, aa + AQ_H);
            ldsm4(Ql_, aa + AQ_L);
#pragma unroll
            for (int ng = 0; ng < 4; ng++) {
                uint32_t Kh_[4], Kl_[4];
                const uint32_t ba = kvb + ng * (16 * 144) + kb_sub + ks * 32;
                ldsm4(Kh_, ba);
                ldsm4(Kl_, ba + 9216);
#pragma unroll
                for (int h2 = 0; h2 < 2; h2++) {
                    const int nt = ng * 2 + h2;
                    mma_bf16(cs[nt], Qh_, &Kh_[h2 * 2]);
                    mma_bf16(cs[nt], Qh_, &Kl_[h2 * 2]);
                    mma_bf16(cs[nt], Ql_, &Kh_[h2 * 2]);
                }
            }
        }

#pragma unroll
        for (int nt = 0; nt < 8; nt++) {
            int2 mv = *(const int2*)(mrow_base + kv0 + nt * 8 + t * 2);
            if (mv.x == 0) { cs[nt][0] = -1e9f; cs[nt][2] = -1e9f; }
            if (mv.y == 0) { cs[nt][1] = -1e9f; cs[nt][3] = -1e9f; }
        }
        float mx0 = cs[0][0], mx1 = cs[0][2];
#pragma unroll
        for (int nt = 0; nt < 8; nt++) {
            mx0 = fmaxf(mx0, fmaxf(cs[nt][0], cs[nt][1]));
            mx1 = fmaxf(mx1, fmaxf(cs[nt][2], cs[nt][3]));
        }
        mx0 = fmaxf(mx0, __shfl_xor_sync(0xffffffffu, mx0, 1));
        mx0 = fmaxf(mx0, __shfl_xor_sync(0xffffffffu, mx0, 2));
        mx1 = fmaxf(mx1, __shfl_xor_sync(0xffffffffu, mx1, 1));
        mx1 = fmaxf(mx1, __shfl_xor_sync(0xffffffffu, mx1, 2));
        const float mn0 = fmaxf(m0, mx0), mn1 = fmaxf(m1, mx1);
        const float f0 = fexp(m0 - mn0), f1 = fexp(m1 - mn1);
        m0 = mn0; m1 = mn1;

        uint32_t phg[8], phg8[8], plg[8], plg8[8];
        float rs0 = 0.f, rs1 = 0.f;
#pragma unroll
        for (int nt = 0; nt < 8; nt++) {
            float p0 = fexp(cs[nt][0] - mn0);
            float p1 = fexp(cs[nt][1] - mn0);
            float p2 = fexp(cs[nt][2] - mn1);
            float p3 = fexp(cs[nt][3] - mn1);
            rs0 += p0 + p1; rs1 += p2 + p3;
            split_pair(p0, p1, phg[nt], plg[nt]);
            split_pair(p2, p3, phg8[nt], plg8[nt]);
        }
        rs0 += __shfl_xor_sync(0xffffffffu, rs0, 1);
        rs0 += __shfl_xor_sync(0xffffffffu, rs0, 2);
        rs1 += __shfl_xor_sync(0xffffffffu, rs1, 1);
        rs1 += __shfl_xor_sync(0xffffffffu, rs1, 2);
        l0 = l0 * f0 + rs0;
        l1 = l1 * f1 + rs1;

#pragma unroll
        for (int nt = 0; nt < 8; nt++) {
            co[nt][0] *= f0; co[nt][1] *= f0;
            co[nt][2] *= f1; co[nt][3] *= f1;
        }

#pragma unroll
        for (int kc = 0; kc < 4; kc++) {
            uint32_t Ah[4] = { phg[2*kc], phg8[2*kc], phg[2*kc+1], phg8[2*kc+1] };
            uint32_t Al[4] = { plg[2*kc], plg8[2*kc], plg[2*kc+1], plg8[2*kc+1] };
#pragma unroll
            for (int ng = 0; ng < 4; ng++) {
                uint32_t Vh_[4], Vl_[4];
                const uint32_t va = kvb + 18432 + kc * (16 * 144) + vb_sub + ng * 32;
                ldsm4t(Vh_, va);
                ldsm4t(Vl_, va + 9216);
#pragma unroll
                for (int h2 = 0; h2 < 2; h2++) {
                    const int nt = ng * 2 + h2;
                    mma_bf16(co[nt], Ah, &Vh_[h2 * 2]);
                    mma_bf16(co[nt], Ah, &Vl_[h2 * 2]);
                    mma_bf16(co[nt], Al, &Vh_[h2 * 2]);
                }
            }
        }
    }

    const float inv0 = 1.0f / l0, inv1 = 1.0f / l1;
    const int r0 = qb * 128 + w * 16 + g;
    const size_t base0 = ((size_t)(b * SEQ + r0)) * D_MODEL + h * 64;
    const size_t base1 = ((size_t)(b * SEQ + r0 + 8)) * D_MODEL + h * 64;
#pragma unroll
    for (int nt = 0; nt < 8; nt++) {
        const int col = nt * 8 + t * 2;
        uint32_t hp, lp;
        split_pair(co[nt][0] * inv0, co[nt][1] * inv0, hp, lp);
        *(uint32_t*)(ctxh + base0 + col) = hp;
        *(uint32_t*)(ctxl + base0 + col) = lp;
        split_pair(co[nt][2] * inv1, co[nt][3] * inv1, hp, lp);
        *(uint32_t*)(ctxh + base1 + col) = hp;
        *(uint32_t*)(ctxl + base1 + col) = lp;
    }
}

// ---------------- LayerNorm (ddof=1, eps added to std); optional bf16 hi/lo out ----------------
__device__ __forceinline__ float warp_sum(float s) {
#pragma unroll
    for (int off = 16; off; off >>= 1) s += __shfl_xor_sync(0xffffffffu, s, off);
    return s;
}

__global__ __launch_bounds__(256)
void ln_kernel(const float* __restrict__ in, const float* __restrict__ alpha,
               const float* __restrict__ beta, float* __restrict__ out,
               __nv_bfloat16* __restrict__ outh, __nv_bfloat16* __restrict__ outl)
{
    __shared__ float red[8];
    const int row = blockIdx.x, tid = threadIdx.x;
    const float* rp = in + (size_t)row * D_MODEL;
    float4 v = *(const float4*)(rp + tid*4);

    float s = v.x + v.y + v.z + v.w;
    s = warp_sum(s);
    if ((tid & 31) == 0) red[tid >> 5] = s;
    __syncthreads();
    float tot = 0.f;
#pragma unroll
    for (int i = 0; i < 8; i++) tot += red[i];
    float mean = tot * (1.0f / 1024.0f);

    float dx = v.x - mean, dy = v.y - mean, dz = v.z - mean, dw = v.w - mean;
    float sq = dx*dx + dy*dy + dz*dz + dw*dw;
    __syncthreads();
    sq = warp_sum(sq);
    if ((tid & 31) == 0) red[tid >> 5] = sq;
    __syncthreads();
    float tot2 = 0.f;
#pragma unroll
    for (int i = 0; i < 8; i++) tot2 += red[i];
    float var  = tot2 * (1.0f / 1023.0f);
    float rstd = 1.0f / (sqrtf(var) + 1e-6f);

    float4 a = *(const float4*)(alpha + tid*4);
    float4 bb = *(const float4*)(beta + tid*4);
    float4 o;
    o.x = a.x * dx * rstd + bb.x;
    o.y = a.y * dy * rstd + bb.y;
    o.z = a.z * dz * rstd + bb.z;
    o.w = a.w * dw * rstd + bb.w;
    *(float4*)(out + (size_t)row * D_MODEL + tid*4) = o;
    if (outh) {
        uint32_t h0, l0, h1, l1;
        split_pair(o.x, o.y, h0, l0);
        split_pair(o.z, o.w, h1, l1);
        *(uint2*)(outh + (size_t)row * D_MODEL + tid*4) = make_uint2(h0, h1);
        *(uint2*)(outl + (size_t)row * D_MODEL + tid*4) = make_uint2(l0, l1);
    }
}

// ---------------- host ----------------
extern "C" void kernel_launch(void* const* d_in, const int* in_sizes, int n_in,
                              void* d_out, int out_size)
{
    const float* x      = (const float*)d_in[0];
    const int*   mask   = (const int*)  d_in[1];
    const float* wq     = (const float*)d_in[2];
    const float* wk     = (const float*)d_in[3];
    const float* wv     = (const float*)d_in[4];
    const float* wo     = (const float*)d_in[5];
    const float* wo_b   = (const float*)d_in[6];
    const float* w1     = (const float*)d_in[7];
    const float* b1     = (const float*)d_in[8];
    const float* w2     = (const float*)d_in[9];
    const float* b2     = (const float*)d_in[10];
    const float* alpha1 = (const float*)d_in[11];
    const float* bias1  = (const float*)d_in[12];
    const float* alpha2 = (const float*)d_in[13];
    const float* bias2  = (const float*)d_in[14];
    float* out = (float*)d_out;

    float *s1, *x1, *s2;
    __nv_bfloat16 *xh, *xl, *qkvh, *qkvl, *ctxh, *ctxl, *x1h, *x1l, *ffh, *ffl;
    __nv_bfloat16 *wqkv_hi, *wqkv_lo, *wo_hi, *wo_lo, *w1_hi, *w1_lo, *w2_hi, *w2_lo;
    cudaGetSymbolAddress((void**)&s1,  g_s1);
    cudaGetSymbolAddress((void**)&x1,  g_x1);
    cudaGetSymbolAddress((void**)&s2,  g_s2);
    cudaGetSymbolAddress((void**)&xh,  g_xh);   cudaGetSymbolAddress((void**)&xl,  g_xl);
    cudaGetSymbolAddress((void**)&qkvh, g_qkvh); cudaGetSymbolAddress((void**)&qkvl, g_qkvl);
    cudaGetSymbolAddress((void**)&ctxh, g_ctxh); cudaGetSymbolAddress((void**)&ctxl, g_ctxl);
    cudaGetSymbolAddress((void**)&x1h, g_x1h);  cudaGetSymbolAddress((void**)&x1l, g_x1l);
    cudaGetSymbolAddress((void**)&ffh, g_ffh);  cudaGetSymbolAddress((void**)&ffl, g_ffl);
    cudaGetSymbolAddress((void**)&wqkv_hi, g_wqkv_hi);
    cudaGetSymbolAddress((void**)&wqkv_lo, g_wqkv_lo);
    cudaGetSymbolAddress((void**)&wo_hi, g_wo_hi);
    cudaGetSymbolAddress((void**)&wo_lo, g_wo_lo);
    cudaGetSymbolAddress((void**)&w1_hi, g_w1_hi);
    cudaGetSymbolAddress((void**)&w1_lo, g_w1_lo);
    cudaGetSymbolAddress((void**)&w2_hi, g_w2_hi);
    cudaGetSymbolAddress((void**)&w2_lo, g_w2_lo);

    // idempotent; no static guards allowed
    cudaFuncSetAttribute(bf16_gemm<1>, cudaFuncAttributeMaxDynamicSharedMemorySize, SMEM_G);
    cudaFuncSetAttribute(bf16_gemm<2>, cudaFuncAttributeMaxDynamicSharedMemorySize, SMEM_G);
    cudaFuncSetAttribute(bf16_gemm<3>, cudaFuncAttributeMaxDynamicSharedMemorySize, SMEM_G);
    cudaFuncSetAttribute(attn_mma,     cudaFuncAttributeMaxDynamicSharedMemorySize, ATSMEM);

    dim3 tblk(32, 8);
    prep_w<<<dim3(D_MODEL/32, D_MODEL/32), tblk>>>(wq, wqkv_hi,                     wqkv_lo,                     D_MODEL, D_MODEL);
    prep_w<<<dim3(D_MODEL/32, D_MODEL/32), tblk>>>(wk, wqkv_hi + D_MODEL*D_MODEL,   wqkv_lo + D_MODEL*D_MODEL,   D_MODEL, D_MODEL);
    prep_w<<<dim3(D_MODEL/32, D_MODEL/32), tblk>>>(wv, wqkv_hi + 2*D_MODEL*D_MODEL, wqkv_lo + 2*D_MODEL*D_MODEL, D_MODEL, D_MODEL);
    prep_w<<<dim3(D_MODEL/32, D_MODEL/32), tblk>>>(wo, wo_hi, wo_lo, D_MODEL, D_MODEL);
    prep_w<<<dim3(DFF/32,     D_MODEL/32), tblk>>>(w1, w1_hi, w1_lo, D_MODEL, DFF);
    prep_w<<<dim3(D_MODEL/32, DFF/32),     tblk>>>(w2, w2_hi, w2_lo, DFF, D_MODEL);

    // split x once
    xsplit<<<(NTOK*D_MODEL)/1024, 256>>>(x, xh, xl);

    // fused QKV projection (N=3072) -> bf16 hi/lo head-transposed, q pre-scaled
    bf16_gemm<1><<<dim3(24, 32), 256, SMEM_G>>>(xh, xl, wqkv_hi, wqkv_lo,
                                                nullptr, nullptr, nullptr, 3*D_MODEL, D_MODEL, qkvh, qkvl);

    attn_mma<<<dim3(SEQ/128, NHEADS, BATCH), 256, ATSMEM>>>(qkvh, qkvl, mask, ctxh, ctxl);

    // O projection + residual, LN1 (emits bf16 for FFN1 A)
    bf16_gemm<2><<<dim3(8, 32), 256, SMEM_G>>>(ctxh, ctxl, wo_hi, wo_lo,
                                               s1, wo_b, x, D_MODEL, D_MODEL, nullptr, nullptr);
    ln_kernel<<<NTOK, 256>>>(s1, alpha1, bias1, x1, x1h, x1l);

    // FFN
    bf16_gemm<3><<<dim3(32, 32), 256, SMEM_G>>>(x1h, x1l, w1_hi, w1_lo,
                                                nullptr, b1, nullptr, DFF, D_MODEL, ffh, ffl);
    bf16_gemm<2><<<dim3(8, 32), 256, SMEM_G>>>(ffh, ffl, w2_hi, w2_lo,
                                               s2, b2, x1, D_MODEL, DFF, nullptr, nullptr);
    ln_kernel<<<NTOK, 256>>>(s2, alpha2, bias2, out, nullptr, nullptr);
}

// round 15
// speedup vs baseline: 3.8202x; 1.0052x over previous
#include <cuda_runtime.h>
#include <cuda_bf16.h>
#include <math.h>
#include <stdint.h>

#define D_MODEL 1024
#define NHEADS  16
#define DK      64
#define SEQ     2048
#define BATCH   2
#define NTOK    (BATCH*SEQ)   // 4096
#define DFF     4096

// ---------------- scratch (no allocations allowed) ----------------
__device__ float g_s1 [NTOK*D_MODEL];
__device__ float g_x1 [NTOK*D_MODEL];
__device__ float g_s2 [NTOK*D_MODEL];

// bf16 hi/lo operand arrays
__device__ __nv_bfloat16 g_xh  [NTOK*D_MODEL];   __device__ __nv_bfloat16 g_xl  [NTOK*D_MODEL];
__device__ __nv_bfloat16 g_qkvh[3*NTOK*D_MODEL]; __device__ __nv_bfloat16 g_qkvl[3*NTOK*D_MODEL];
__device__ __nv_bfloat16 g_ctxh[NTOK*D_MODEL];   __device__ __nv_bfloat16 g_ctxl[NTOK*D_MODEL];
__device__ __nv_bfloat16 g_x1h [NTOK*D_MODEL];   __device__ __nv_bfloat16 g_x1l [NTOK*D_MODEL];
__device__ __nv_bfloat16 g_ffh [NTOK*DFF];       __device__ __nv_bfloat16 g_ffl [NTOK*DFF];

// pre-split transposed weights [N][K], bf16 hi/lo
__device__ __nv_bfloat16 g_wqkv_hi[3*D_MODEL*D_MODEL];
__device__ __nv_bfloat16 g_wqkv_lo[3*D_MODEL*D_MODEL];
__device__ __nv_bfloat16 g_wo_hi  [D_MODEL*D_MODEL];
__device__ __nv_bfloat16 g_wo_lo  [D_MODEL*D_MODEL];
__device__ __nv_bfloat16 g_w1_hi  [DFF*D_MODEL];
__device__ __nv_bfloat16 g_w1_lo  [DFF*D_MODEL];
__device__ __nv_bfloat16 g_w2_hi  [D_MODEL*DFF];
__device__ __nv_bfloat16 g_w2_lo  [D_MODEL*DFF];

// ---------------- helpers ----------------
__device__ __forceinline__ uint32_t smem_u32(const void* p) {
    uint32_t a;
    asm("{ .reg .u64 t; cvta.to.shared.u64 t, %1; cvt.u32.u64 %0, t; }" : "=r"(a) : "l"(p));
    return a;
}
__device__ __forceinline__ void ldsm4(uint32_t* r, uint32_t addr) {
    asm volatile("ldmatrix.sync.aligned.m8n8.x4.shared.b16 {%0,%1,%2,%3}, [%4];"
        : "=r"(r[0]), "=r"(r[1]), "=r"(r[2]), "=r"(r[3]) : "r"(addr));
}
__device__ __forceinline__ void ldsm4t(uint32_t* r, uint32_t addr) {
    asm volatile("ldmatrix.sync.aligned.m8n8.x4.trans.shared.b16 {%0,%1,%2,%3}, [%4];"
        : "=r"(r[0]), "=r"(r[1]), "=r"(r[2]), "=r"(r[3]) : "r"(addr));
}
__device__ __forceinline__ void mma_bf16(float* d, const uint32_t* a, const uint32_t* b) {
    asm volatile(
        "mma.sync.aligned.m16n8k16.row.col.f32.bf16.bf16.f32 "
        "{%0,%1,%2,%3}, {%4,%5,%6,%7}, {%8,%9}, {%0,%1,%2,%3};"
        : "+f"(d[0]), "+f"(d[1]), "+f"(d[2]), "+f"(d[3])
        : "r"(a[0]), "r"(a[1]), "r"(a[2]), "r"(a[3]), "r"(b[0]), "r"(b[1]));
}
__device__ __forceinline__ uint32_t packbf2(float x, float y) {
    __nv_bfloat162 h = __floats2bfloat162_rn(x, y);
    return *(uint32_t*)&h;
}
__device__ __forceinline__ uint32_t packbf16pair(__nv_bfloat16 a, __nv_bfloat16 b) {
    return (uint32_t)__bfloat16_as_ushort(a) | ((uint32_t)__bfloat16_as_ushort(b) << 16);
}
__device__ __forceinline__ float fexp(float x) {
    float y = x * 1.4426950408889634f;
    y = fmaxf(y, -126.0f);
    float t = y + 12582912.0f;
    int   n = __float_as_int(t) - 0x4B400000;
    float f = y - (t - 12582912.0f);
    float p = 1.3333558146428443e-3f;
    p = fmaf(p, f, 9.6181291076284772e-3f);
    p = fmaf(p, f, 5.5504108664821580e-2f);
    p = fmaf(p, f, 2.4022650695910072e-1f);
    p = fmaf(p, f, 6.9314718055994531e-1f);
    p = fmaf(p, f, 1.0f);
    return __int_as_float(__float_as_int(p) + (n << 23));
}
__device__ __forceinline__ void split_pair(float v0, float v1, uint32_t& hp, uint32_t& lp) {
    __nv_bfloat16 h0 = __float2bfloat16(v0), h1 = __float2bfloat16(v1);
    hp = packbf16pair(h0, h1);
    lp = packbf2(v0 - __bfloat162float(h0), v1 - __bfloat162float(h1));
}

// ---------------- elementwise fp32 -> bf16 hi/lo split ----------------
__global__ __launch_bounds__(256)
void xsplit(const float* __restrict__ A, __nv_bfloat16* __restrict__ H,
            __nv_bfloat16* __restrict__ L)
{
    const size_t i = ((size_t)blockIdx.x * 256 + threadIdx.x) * 4;
    float4 v = *(const float4*)(A + i);
    uint32_t h0, l0, h1, l1;
    split_pair(v.x, v.y, h0, l0);
    split_pair(v.z, v.w, h1, l1);
    *(uint2*)(H + i) = make_uint2(h0, h1);
    *(uint2*)(L + i) = make_uint2(l0, l1);
}

// ---------------- weight prep: W[K][N] fp32 -> T[N][K] bf16 hi/lo ----------------
__global__ void prep_w(const float* __restrict__ W, __nv_bfloat16* __restrict__ Thi,
                       __nv_bfloat16* __restrict__ Tlo, int K, int N)
{
    __shared__ float t[32][33];
    const int k0 = blockIdx.y * 32, n0 = blockIdx.x * 32;
    const int tx = threadIdx.x, ty = threadIdx.y;
#pragma unroll
    for (int r = 0; r < 4; r++)
        t[ty + 8*r][tx] = W[(size_t)(k0 + ty + 8*r) * N + n0 + tx];
    __syncthreads();
#pragma unroll
    for (int r = 0; r < 4; r++) {
        const int n = n0 + ty + 8*r, k = k0 + tx;
        float x = t[tx][ty + 8*r];
        __nv_bfloat16 hi = __float2bfloat16(x);
        __nv_bfloat16 lo = __float2bfloat16(x - __bfloat162float(hi));
        Thi[(size_t)n * K + k] = hi;
        Tlo[(size_t)n * K + k] = lo;
    }
}

// ---------------- bf16x3 mma.sync GEMM, 4-stage cp.async ring ----------------
// C[M,N] = (Ahi+Alo)[M,K] @ (Bhi+Blo)[N,K]^T  via hh+hl+lh
// Block 128x128, BK=32, 8 warps (2m x 4n), warp tile 64x32.
// smem per stage: Ah/Al/Bh/Bl each [128 rows][32 bf16] pad 80B = 10240B -> 40960B
// 4 stages = 163840B (1 CTA/SM). wait_group 2 -> ~2 iterations of latency hiding.
#define GS_BUF   40960
#define SMEM_G   (4*GS_BUF)

template<int EPI>
__global__ __launch_bounds__(256, 1)
void bf16_gemm(const __nv_bfloat16* __restrict__ Ahi, const __nv_bfloat16* __restrict__ Alo,
               const __nv_bfloat16* __restrict__ Bhi, const __nv_bfloat16* __restrict__ Blo,
               float* __restrict__ C, const float* __restrict__ bias,
               const float* __restrict__ res, int N, int K,
               __nv_bfloat16* __restrict__ Ohi, __nv_bfloat16* __restrict__ Olo)
{
    extern __shared__ char smem[];
    const uint32_t sbase = smem_u32(smem);
    const int tid = threadIdx.x, wid = tid >> 5, lane = tid & 31;
    const int g = lane >> 2, t = lane & 3;
    const int wm = wid >> 2, wn = wid & 3;
    const int bm = blockIdx.y, bn = blockIdx.x;

    float c[4][4][4];
#pragma unroll
    for (int mt = 0; mt < 4; mt++)
#pragma unroll
        for (int nt = 0; nt < 4; nt++)
#pragma unroll
            for (int f = 0; f < 4; f++) c[mt][nt][f] = 0.f;

    auto cp_all = [&](int buf, int kb) {
#pragma unroll
        for (int j = 0; j < 8; j++) {
            const int cidx = tid + 256 * j;
            const int arr = cidx >> 9;      // 0:Ah 1:Al 2:Bh 3:Bl
            const int cc  = cidx & 511;
            const int row = cc >> 2, kc = cc & 3;
            const __nv_bfloat16* gp = (arr == 0 ? Ahi : arr == 1 ? Alo : arr == 2 ? Bhi : Blo);
            const int base = (arr < 2 ? bm : bn) * 128;
            const __nv_bfloat16* src = gp + (size_t)(base + row) * K + kb * 32 + kc * 8;
            const uint32_t dst = sbase + buf * GS_BUF + arr * 10240 + row * 80 + kc * 16;
            asm volatile("cp.async.cg.shared.global [%0], [%1], 16;\n" :: "r"(dst), "l"(src));
        }
        asm volatile("cp.async.commit_group;\n");
    };

    const uint32_t a_off = (uint32_t)((wm * 64 + (lane & 15)) * 80 + ((lane >> 4) << 4));
    const uint32_t b_off = (uint32_t)((wn * 32 + ((lane >> 4) << 3) + (lane & 7)) * 80
                                      + (((lane >> 3) & 1) << 4));

    const int niter = K >> 5;
    cp_all(0, 0);
    if (niter > 1) cp_all(1, 1);
    if (niter > 2) cp_all(2, 2);

    for (int it = 0; it < niter; it++) {
        const int buf = it & 3;
        asm volatile("cp.async.wait_group 2;\n");   // tile `it` complete; 2 younger in flight
        __syncthreads();                            // all warps past compute(it-1); buf (it+3)&3 free
        if (it + 3 < niter) cp_all((it + 3) & 3, it + 3);

        const uint32_t sb = sbase + buf * GS_BUF;
#pragma unroll
        for (int ks = 0; ks < 2; ks++) {
            uint32_t Ah[4][4], Al[4][4], Bh[2][4], Bl[2][4];
#pragma unroll
            for (int mt = 0; mt < 4; mt++) {
                const uint32_t aa = sb + a_off + mt * (16 * 80) + ks * 32;
                ldsm4(Ah[mt], aa);
                ldsm4(Al[mt], aa + 10240);
            }
#pragma unroll
            for (int ng = 0; ng < 2; ng++) {
                const uint32_t ba = sb + b_off + ng * (16 * 80) + ks * 32;
                ldsm4(Bh[ng], ba + 20480);
                ldsm4(Bl[ng], ba + 30720);
            }
#pragma unroll
            for (int mt = 0; mt < 4; mt++)
#pragma unroll
                for (int nt = 0; nt < 4; nt++) {
                    const uint32_t* bh = &Bh[nt >> 1][(nt & 1) * 2];
                    const uint32_t* bl = &Bl[nt >> 1][(nt & 1) * 2];
                    mma_bf16(c[mt][nt], Ah[mt], bh);   // hi*hi
                    mma_bf16(c[mt][nt], Ah[mt], bl);   // hi*lo
                    mma_bf16(c[mt][nt], Al[mt], bh);   // lo*hi
                }
        }
    }

    // ---------------- epilogue ----------------
#pragma unroll
    for (int mt = 0; mt < 4; mt++) {
        const int r0 = bm * 128 + wm * 64 + mt * 16 + g;
#pragma unroll
        for (int nt = 0; nt < 4; nt++) {
            const int c0 = bn * 128 + wn * 32 + nt * 8 + t * 2;
#pragma unroll
            for (int half = 0; half < 2; half++) {
                const int r = r0 + half * 8;
                float v0 = c[mt][nt][half * 2], v1 = c[mt][nt][half * 2 + 1];
                if (EPI == 1) {
                    const int which = c0 >> 10, cm = c0 & 1023;
                    if (which == 0) { v0 *= 0.125f; v1 *= 0.125f; }
                    uint32_t hp, lp;
                    split_pair(v0, v1, hp, lp);
                    const size_t idx = (size_t)which * (NTOK * D_MODEL)
                        + (((size_t)((r >> 11) * NHEADS + (cm >> 6)) * SEQ + (r & 2047)) * DK + (cm & 63));
                    *(uint32_t*)(Ohi + idx) = hp;
                    *(uint32_t*)(Olo + idx) = lp;
                } else if (EPI == 2) {
                    const float* rs = res + (size_t)r * N + c0;
                    C[(size_t)r * N + c0]     = v0 + bias[c0]     + rs[0];
                    C[(size_t)r * N + c0 + 1] = v1 + bias[c0 + 1] + rs[1];
                } else { // 3: relu -> bf16 hi/lo
                    float a0 = fmaxf(v0 + bias[c0], 0.f);
                    float a1 = fmaxf(v1 + bias[c0 + 1], 0.f);
                    uint32_t hp, lp;
                    split_pair(a0, a1, hp, lp);
                    const size_t idx = (size_t)r * N + c0;
                    *(uint32_t*)(Ohi + idx) = hp;
                    *(uint32_t*)(Olo + idx) = lp;
                }
            }
        }
    }
}

// ---------------- FA2-style tensor-core attention (proven; bf16 ctx out) ----------------
#define AQ_H   0
#define AQ_L   18432
#define AKV    36864
#define AKVBUF 36864
#define ATSMEM (36864 + 2*36864)

__global__ __launch_bounds__(256, 2)
void attn_mma(const __nv_bfloat16* __restrict__ qkvh, const __nv_bfloat16* __restrict__ qkvl,
              const int* __restrict__ mask,
              __nv_bfloat16* __restrict__ ctxh, __nv_bfloat16* __restrict__ ctxl)
{
    extern __shared__ char sm[];
    const uint32_t sb = smem_u32(sm);
    const int tid = threadIdx.x, w = tid >> 5, lane = tid & 31;
    const int g = lane >> 2, t = lane & 3;
    const int qb = blockIdx.x, h = blockIdx.y, b = blockIdx.z;
    const size_t hoff = ((size_t)(b * NHEADS + h)) * SEQ * DK;

    const __nv_bfloat16* qh = qkvh + hoff + (size_t)qb * 128 * DK;
    const __nv_bfloat16* ql = qkvl + hoff + (size_t)qb * 128 * DK;
    const __nv_bfloat16* kh = qkvh + (size_t)NTOK * D_MODEL + hoff;
    const __nv_bfloat16* kl = qkvl + (size_t)NTOK * D_MODEL + hoff;
    const __nv_bfloat16* vh = qkvh + (size_t)2 * NTOK * D_MODEL + hoff;
    const __nv_bfloat16* vl = qkvl + (size_t)2 * NTOK * D_MODEL + hoff;

#pragma unroll
    for (int j = 0; j < 8; j++) {
        const int cidx = tid + j * 256;
        const int arr = cidx >> 10, cc = cidx & 1023;
        const int row = cc >> 3, k8 = cc & 7;
        const __nv_bfloat16* src = (arr == 0 ? qh : ql) + row * DK + k8 * 8;
        *(uint4*)(sm + AQ_H + arr * 18432 + row * 144 + k8 * 16) = *(const uint4*)src;
    }

    auto prefetch_kv = [&](int buf, int kv0) {
#pragma unroll
        for (int j = 0; j < 8; j++) {
            const int cidx = tid + j * 256;
            const int arr = cidx >> 9, cc = cidx & 511;
            const int row = cc >> 3, k8 = cc & 7;
            const __nv_bfloat16* src =
                (arr == 0 ? kh : arr == 1 ? kl : arr == 2 ? vh : vl)
                + (size_t)(kv0 + row) * DK + k8 * 8;
            const uint32_t dst = sb + AKV + buf * AKVBUF + arr * 9216 + row * 144 + k8 * 16;
            asm volatile("cp.async.cg.shared.global [%0], [%1], 16;\n" :: "r"(dst), "l"(src));
        }
        asm volatile("cp.async.commit_group;\n");
    };

    prefetch_kv(0, 0);

    float m0 = -1e30f, m1 = -1e30f, l0 = 0.f, l1 = 0.f;
    float co[8][4];
#pragma unroll
    for (int nt = 0; nt < 8; nt++)
#pragma unroll
        for (int f = 0; f < 4; f++) co[nt][f] = 0.f;

    const uint32_t qa_off = (uint32_t)((w * 16 + (lane & 15)) * 144 + ((lane >> 4) << 4));
    const uint32_t kb_sub = (uint32_t)((((lane >> 4) << 3) + (lane & 7)) * 144
                                       + (((lane >> 3) & 1) << 4));
    const uint32_t vb_sub = (uint32_t)(((((lane >> 3) & 1) << 3) + (lane & 7)) * 144
                                       + ((lane >> 4) << 4));
    const int* mrow_base = mask + b * SEQ;

    for (int it = 0; it < SEQ / 64; it++) {
        const int buf = it & 1;
        const int kv0 = it * 64;
        asm volatile("cp.async.wait_group 0;\n");
        __syncthreads();
        if (it + 1 < SEQ / 64) prefetch_kv(buf ^ 1, kv0 + 64);

        const uint32_t kvb = sb + AKV + buf * AKVBUF;

        float cs[8][4];
#pragma unroll
        for (int nt = 0; nt < 8; nt++)
#pragma unroll
            for (int f = 0; f < 4; f++) cs[nt][f] = 0.f;
#pragma unroll
        for (int ks = 0; ks < 4; ks++) {
            uint32_t Qh_[4], Ql_[4];
            const uint32_t aa = sb + qa_off + ks * 32;
            ldsm4(Qh_, aa + AQ_H);
            ldsm4(Ql_, aa + AQ_L);
#pragma unroll
            for (int ng = 0; ng < 4; ng++) {
                uint32_t Kh_[4], Kl_[4];
                const uint32_t ba = kvb + ng * (16 * 144) + kb_sub + ks * 32;
                ldsm4(Kh_, ba);
                ldsm4(Kl_, ba + 9216);
#pragma unroll
                for (int h2 = 0; h2 < 2; h2++) {
                    const int nt = ng * 2 + h2;
                    mma_bf16(cs[nt], Qh_, &Kh_[h2 * 2]);
                    mma_bf16(cs[nt], Qh_, &Kl_[h2 * 2]);
                    mma_bf16(cs[nt], Ql_, &Kh_[h2 * 2]);
                }
            }
        }

#pragma unroll
        for (int nt = 0; nt < 8; nt++) {
            int2 mv = *(const int2*)(mrow_base + kv0 + nt * 8 + t * 2);
            if (mv.x == 0) { cs[nt][0] = -1e9f; cs[nt][2] = -1e9f; }
            if (mv.y == 0) { cs[nt][1] = -1e9f; cs[nt][3] = -1e9f; }
        }
        float mx0 = cs[0][0], mx1 = cs[0][2];
#pragma unroll
        for (int nt = 0; nt < 8; nt++) {
            mx0 = fmaxf(mx0, fmaxf(cs[nt][0], cs[nt][1]));
            mx1 = fmaxf(mx1, fmaxf(cs[nt][2], cs[nt][3]));
        }
        mx0 = fmaxf(mx0, __shfl_xor_sync(0xffffffffu, mx0, 1));
        mx0 = fmaxf(mx0, __shfl_xor_sync(0xffffffffu, mx0, 2));
        mx1 = fmaxf(mx1, __shfl_xor_sync(0xffffffffu, mx1, 1));
        mx1 = fmaxf(mx1, __shfl_xor_sync(0xffffffffu, mx1, 2));
        const float mn0 = fmaxf(m0, mx0), mn1 = fmaxf(m1, mx1);
        const float f0 = fexp(m0 - mn0), f1 = fexp(m1 - mn1);
        m0 = mn0; m1 = mn1;

        uint32_t phg[8], phg8[8], plg[8], plg8[8];
        float rs0 = 0.f, rs1 = 0.f;
#pragma unroll
        for (int nt = 0; nt < 8; nt++) {
            float p0 = fexp(cs[nt][0] - mn0);
            float p1 = fexp(cs[nt][1] - mn0);
            float p2 = fexp(cs[nt][2] - mn1);
            float p3 = fexp(cs[nt][3] - mn1);
            rs0 += p0 + p1; rs1 += p2 + p3;
            split_pair(p0, p1, phg[nt], plg[nt]);
            split_pair(p2, p3, phg8[nt], plg8[nt]);
        }
        rs0 += __shfl_xor_sync(0xffffffffu, rs0, 1);
        rs0 += __shfl_xor_sync(0xffffffffu, rs0, 2);
        rs1 += __shfl_xor_sync(0xffffffffu, rs1, 1);
        rs1 += __shfl_xor_sync(0xffffffffu, rs1, 2);
        l0 = l0 * f0 + rs0;
        l1 = l1 * f1 + rs1;

#pragma unroll
        for (int nt = 0; nt < 8; nt++) {
            co[nt][0] *= f0; co[nt][1] *= f0;
            co[nt][2] *= f1; co[nt][3] *= f1;
        }

#pragma unroll
        for (int kc = 0; kc < 4; kc++) {
            uint32_t Ah[4] = { phg[2*kc], phg8[2*kc], phg[2*kc+1], phg8[2*kc+1] };
            uint32_t Al[4] = { plg[2*kc], plg8[2*kc], plg[2*kc+1], plg8[2*kc+1] };
#pragma unroll
            for (int ng = 0; ng < 4; ng++) {
                uint32_t Vh_[4], Vl_[4];
                const uint32_t va = kvb + 18432 + kc * (16 * 144) + vb_sub + ng * 32;
                ldsm4t(Vh_, va);
                ldsm4t(Vl_, va + 9216);
#pragma unroll
                for (int h2 = 0; h2 < 2; h2++) {
                    const int nt = ng * 2 + h2;
                    mma_bf16(co[nt], Ah, &Vh_[h2 * 2]);
                    mma_bf16(co[nt], Ah, &Vl_[h2 * 2]);
                    mma_bf16(co[nt], Al, &Vh_[h2 * 2]);
                }
            }
        }
    }

    const float inv0 = 1.0f / l0, inv1 = 1.0f / l1;
    const int r0 = qb * 128 + w * 16 + g;
    const size_t base0 = ((size_t)(b * SEQ + r0)) * D_MODEL + h * 64;
    const size_t base1 = ((size_t)(b * SEQ + r0 + 8)) * D_MODEL + h * 64;
#pragma unroll
    for (int nt = 0; nt < 8; nt++) {
        const int col = nt * 8 + t * 2;
        uint32_t hp, lp;
        split_pair(co[nt][0] * inv0, co[nt][1] * inv0, hp, lp);
        *(uint32_t*)(ctxh + base0 + col) = hp;
        *(uint32_t*)(ctxl + base0 + col) = lp;
        split_pair(co[nt][2] * inv1, co[nt][3] * inv1, hp, lp);
        *(uint32_t*)(ctxh + base1 + col) = hp;
        *(uint32_t*)(ctxl + base1 + col) = lp;
    }
}

// ---------------- LayerNorm (ddof=1, eps added to std); optional bf16 hi/lo out ----------------
__device__ __forceinline__ float warp_sum(float s) {
#pragma unroll
    for (int off = 16; off; off >>= 1) s += __shfl_xor_sync(0xffffffffu, s, off);
    return s;
}

__global__ __launch_bounds__(256)
void ln_kernel(const float* __restrict__ in, const float* __restrict__ alpha,
               const float* __restrict__ beta, float* __restrict__ out,
               __nv_bfloat16* __restrict__ outh, __nv_bfloat16* __restrict__ outl)
{
    __shared__ float red[8];
    const int row = blockIdx.x, tid = threadIdx.x;
    const float* rp = in + (size_t)row * D_MODEL;
    float4 v = *(const float4*)(rp + tid*4);

    float s = v.x + v.y + v.z + v.w;
    s = warp_sum(s);
    if ((tid & 31) == 0) red[tid >> 5] = s;
    __syncthreads();
    float tot = 0.f;
#pragma unroll
    for (int i = 0; i < 8; i++) tot += red[i];
    float mean = tot * (1.0f / 1024.0f);

    float dx = v.x - mean, dy = v.y - mean, dz = v.z - mean, dw = v.w - mean;
    float sq = dx*dx + dy*dy + dz*dz + dw*dw;
    __syncthreads();
    sq = warp_sum(sq);
    if ((tid & 31) == 0) red[tid >> 5] = sq;
    __syncthreads();
    float tot2 = 0.f;
#pragma unroll
    for (int i = 0; i < 8; i++) tot2 += red[i];
    float var  = tot2 * (1.0f / 1023.0f);
    float rstd = 1.0f / (sqrtf(var) + 1e-6f);

    float4 a = *(const float4*)(alpha + tid*4);
    float4 bb = *(const float4*)(beta + tid*4);
    float4 o;
    o.x = a.x * dx * rstd + bb.x;
    o.y = a.y * dy * rstd + bb.y;
    o.z = a.z * dz * rstd + bb.z;
    o.w = a.w * dw * rstd + bb.w;
    *(float4*)(out + (size_t)row * D_MODEL + tid*4) = o;
    if (outh) {
        uint32_t h0, l0, h1, l1;
        split_pair(o.x, o.y, h0, l0);
        split_pair(o.z, o.w, h1, l1);
        *(uint2*)(outh + (size_t)row * D_MODEL + tid*4) = make_uint2(h0, h1);
        *(uint2*)(outl + (size_t)row * D_MODEL + tid*4) = make_uint2(l0, l1);
    }
}

// ---------------- host ----------------
extern "C" void kernel_launch(void* const* d_in, const int* in_sizes, int n_in,
                              void* d_out, int out_size)
{
    const float* x      = (const float*)d_in[0];
    const int*   mask   = (const int*)  d_in[1];
    const float* wq     = (const float*)d_in[2];
    const float* wk     = (const float*)d_in[3];
    const float* wv     = (const float*)d_in[4];
    const float* wo     = (const float*)d_in[5];
    const float* wo_b   = (const float*)d_in[6];
    const float* w1     = (const float*)d_in[7];
    const float* b1     = (const float*)d_in[8];
    const float* w2     = (const float*)d_in[9];
    const float* b2     = (const float*)d_in[10];
    const float* alpha1 = (const float*)d_in[11];
    const float* bias1  = (const float*)d_in[12];
    const float* alpha2 = (const float*)d_in[13];
    const float* bias2  = (const float*)d_in[14];
    float* out = (float*)d_out;

    float *s1, *x1, *s2;
    __nv_bfloat16 *xh, *xl, *qkvh, *qkvl, *ctxh, *ctxl, *x1h, *x1l, *ffh, *ffl;
    __nv_bfloat16 *wqkv_hi, *wqkv_lo, *wo_hi, *wo_lo, *w1_hi, *w1_lo, *w2_hi, *w2_lo;
    cudaGetSymbolAddress((void**)&s1,  g_s1);
    cudaGetSymbolAddress((void**)&x1,  g_x1);
    cudaGetSymbolAddress((void**)&s2,  g_s2);
    cudaGetSymbolAddress((void**)&xh,  g_xh);   cudaGetSymbolAddress((void**)&xl,  g_xl);
    cudaGetSymbolAddress((void**)&qkvh, g_qkvh); cudaGetSymbolAddress((void**)&qkvl, g_qkvl);
    cudaGetSymbolAddress((void**)&ctxh, g_ctxh); cudaGetSymbolAddress((void**)&ctxl, g_ctxl);
    cudaGetSymbolAddress((void**)&x1h, g_x1h);  cudaGetSymbolAddress((void**)&x1l, g_x1l);
    cudaGetSymbolAddress((void**)&ffh, g_ffh);  cudaGetSymbolAddress((void**)&ffl, g_ffl);
    cudaGetSymbolAddress((void**)&wqkv_hi, g_wqkv_hi);
    cudaGetSymbolAddress((void**)&wqkv_lo, g_wqkv_lo);
    cudaGetSymbolAddress((void**)&wo_hi, g_wo_hi);
    cudaGetSymbolAddress((void**)&wo_lo, g_wo_lo);
    cudaGetSymbolAddress((void**)&w1_hi, g_w1_hi);
    cudaGetSymbolAddress((void**)&w1_lo, g_w1_lo);
    cudaGetSymbolAddress((void**)&w2_hi, g_w2_hi);
    cudaGetSymbolAddress((void**)&w2_lo, g_w2_lo);

    // idempotent; no static guards allowed
    cudaFuncSetAttribute(bf16_gemm<1>, cudaFuncAttributeMaxDynamicSharedMemorySize, SMEM_G);
    cudaFuncSetAttribute(bf16_gemm<2>, cudaFuncAttributeMaxDynamicSharedMemorySize, SMEM_G);
    cudaFuncSetAttribute(bf16_gemm<3>, cudaFuncAttributeMaxDynamicSharedMemorySize, SMEM_G);
    cudaFuncSetAttribute(attn_mma,     cudaFuncAttributeMaxDynamicSharedMemorySize, ATSMEM);

    dim3 tblk(32, 8);
    prep_w<<<dim3(D_MODEL/32, D_MODEL/32), tblk>>>(wq, wqkv_hi,                     wqkv_lo,                     D_MODEL, D_MODEL);
    prep_w<<<dim3(D_MODEL/32, D_MODEL/32), tblk>>>(wk, wqkv_hi + D_MODEL*D_MODEL,   wqkv_lo + D_MODEL*D_MODEL,   D_MODEL, D_MODEL);
    prep_w<<<dim3(D_MODEL/32, D_MODEL/32), tblk>>>(wv, wqkv_hi + 2*D_MODEL*D_MODEL, wqkv_lo + 2*D_MODEL*D_MODEL, D_MODEL, D_MODEL);
    prep_w<<<dim3(D_MODEL/32, D_MODEL/32), tblk>>>(wo, wo_hi, wo_lo, D_MODEL, D_MODEL);
    prep_w<<<dim3(DFF/32,     D_MODEL/32), tblk>>>(w1, w1_hi, w1_lo, D_MODEL, DFF);
    prep_w<<<dim3(D_MODEL/32, DFF/32),     tblk>>>(w2, w2_hi, w2_lo, DFF, D_MODEL);

    // split x once
    xsplit<<<(NTOK*D_MODEL)/1024, 256>>>(x, xh, xl);

    // fused QKV projection (N=3072) -> bf16 hi/lo head-transposed, q pre-scaled
    bf16_gemm<1><<<dim3(24, 32), 256, SMEM_G>>>(xh, xl, wqkv_hi, wqkv_lo,
                                                nullptr, nullptr, nullptr, 3*D_MODEL, D_MODEL, qkvh, qkvl);

    attn_mma<<<dim3(SEQ/128, NHEADS, BATCH), 256, ATSMEM>>>(qkvh, qkvl, mask, ctxh, ctxl);

    // O projection + residual, LN1 (emits bf16 for FFN1 A)
    bf16_gemm<2><<<dim3(8, 32), 256, SMEM_G>>>(ctxh, ctxl, wo_hi, wo_lo,
                                               s1, wo_b, x, D_MODEL, D_MODEL, nullptr, nullptr);
    ln_kernel<<<NTOK, 256>>>(s1, alpha1, bias1, x1, x1h, x1l);

    // FFN
    bf16_gemm<3><<<dim3(32, 32), 256, SMEM_G>>>(x1h, x1l, w1_hi, w1_lo,
                                                nullptr, b1, nullptr, DFF, D_MODEL, ffh, ffl);
    bf16_gemm<2><<<dim3(8, 32), 256, SMEM_G>>>(ffh, ffl, w2_hi, w2_lo,
                                               s2, b2, x1, D_MODEL, DFF, nullptr, nullptr);
    ln_kernel<<<NTOK, 256>>>(s2, alpha2, bias2, out, nullptr, nullptr);
}